// round 11
// baseline (speedup 1.0000x reference)
#include <cuda_runtime.h>
#include <cstdint>

// MonarchOutProjection:
//   h2[t][b][n]    = sum_m L[b][n][m] * x[t][m*32+b]
//   out[t][i*32+j] = sum_m R[j][i][m] * h2[t][m][j]
//
// R10: R=4 output rows per thread (weights = 64 packed u64 regs), 128-thread
// CTAs x 3/SM. Crossbar (the measured wall: replicated bytes at 128B/cyc/SM)
// per output halves vs R9. Diagonal FFMA2 packing keeps issue under crossbar.
// CTA owns an eighth (4 blocks); thread = (nh in [0,8), th in [0,4)):
// rows nh+8r (r<4), t in [4th, 4th+4).

#define TILE_T 16
#define BROWS 516                      // per-block smem row: 32m*16t + 4
#define XS_FLOATS (4 * BROWS)          // 2064 per buffer (4 blocks)
#define OS_FLOATS (16 * 132)           // 2112: os[t][i][jl] = t*132 + i*4 + jl
#define SMEM1_BYTES (2 * XS_FLOATS * 4)                 // 16512
#define SMEM2_BYTES ((2 * XS_FLOATS + OS_FLOATS) * 4)   // 24960

// g_h2[tile][b][n][t] : idx = tile*16384 + b*512 + n*16 + t
__device__ float g_h2[33554432];

__device__ __forceinline__ unsigned smem_addr(const void* p) {
    return (unsigned)__cvta_generic_to_shared(p);
}
__device__ __forceinline__ void cp_async4(unsigned dst, const float* src) {
    asm volatile("cp.async.ca.shared.global [%0], [%1], 4;" :: "r"(dst), "l"(src));
}
__device__ __forceinline__ void cp_async16(unsigned dst, const float* src) {
    asm volatile("cp.async.cg.shared.global [%0], [%1], 16;" :: "r"(dst), "l"(src));
}
__device__ __forceinline__ void cp_commit() {
    asm volatile("cp.async.commit_group;");
}
__device__ __forceinline__ void cp_wait0() {
    asm volatile("cp.async.wait_group 0;");
}
__device__ __forceinline__ void ffma2(uint64_t& acc, uint64_t a, uint64_t b) {
    asm("fma.rn.f32x2 %0, %1, %2, %0;" : "+l"(acc) : "l"(a), "l"(b));
}
__device__ __forceinline__ uint64_t pack2(float lo, float hi) {
    uint64_t r;
    asm("mov.b64 %0, {%1, %2};" : "=l"(r) : "f"(lo), "f"(hi));
    return r;
}
__device__ __forceinline__ float2 bc2(uint64_t v) {
    float2 f; *(uint64_t*)&f = v; return f;
}

// Load 4 weight rows W[base + (nh+8r)*32 + m] packed as row-pairs:
// Wp[p][m] = {row 2p, row 2p+1}.
__device__ __forceinline__ void load_wpacked(const float* Wbase, int nh,
                                             uint64_t Wp[2][32]) {
    #pragma unroll
    for (int p = 0; p < 2; p++) {
        float r0[32], r1[32];
        const float4* p0 = (const float4*)(Wbase + (nh + 8 * (2 * p)) * 32);
        const float4* p1 = (const float4*)(Wbase + (nh + 8 * (2 * p + 1)) * 32);
        #pragma unroll
        for (int g = 0; g < 8; g++) {
            float4 a = p0[g], b = p1[g];
            r0[4*g] = a.x; r0[4*g+1] = a.y; r0[4*g+2] = a.z; r0[4*g+3] = a.w;
            r1[4*g] = b.x; r1[4*g+1] = b.y; r1[4*g+2] = b.z; r1[4*g+3] = b.w;
        }
        #pragma unroll
        for (int m = 0; m < 32; m++) Wp[p][m] = pack2(r0[m], r1[m]);
    }
}

// 8-FFMA2 diagonal core for one m. xv = {x0,x1},{x2,x3}; s0={x1,x0}, s1={x3,x2}.
// accD[p][tp] = {row2p @ t2tp,   row2p+1 @ t2tp+1}
// accS[p][tp] = {row2p @ t2tp+1, row2p+1 @ t2tp}
__device__ __forceinline__ void mma_core(const uint64_t Wp[2][32], int m,
                                         ulonglong2 xv,
                                         uint64_t accD[2][2], uint64_t accS[2][2]) {
    float2 f01 = bc2(xv.x), f23 = bc2(xv.y);
    uint64_t s0 = pack2(f01.y, f01.x);
    uint64_t s1 = pack2(f23.y, f23.x);
    ffma2(accD[0][0], Wp[0][m], xv.x);
    ffma2(accS[0][0], Wp[0][m], s0);
    ffma2(accD[0][1], Wp[0][m], xv.y);
    ffma2(accS[0][1], Wp[0][m], s1);
    ffma2(accD[1][0], Wp[1][m], xv.x);
    ffma2(accS[1][0], Wp[1][m], s0);
    ffma2(accD[1][1], Wp[1][m], xv.y);
    ffma2(accS[1][1], Wp[1][m], s1);
}

__global__ __launch_bounds__(128, 3)
void monarch_stage1(const float* __restrict__ x, const float* __restrict__ L,
                    int ntiles) {
    extern __shared__ float sm[];        // buf0|buf1 : xs[bl][m][tq-slot][.]
    const int tid  = threadIdx.x;
    const int warp = tid >> 5;           // bl in [0,4)
    const int lane = tid & 31;
    const int nh = lane & 7, th = lane >> 3;
    const int s  = blockIdx.x & 7;       // eighth: blocks [4s, 4s+4)
    const int b  = 4 * s + warp;

    uint64_t Wp[2][32];
    load_wpacked(L + b * 1024, nh, Wp);

    const unsigned sbase = smem_addr(sm);
    const int tstep = gridDim.x >> 3;
    const int tile0 = blockIdx.x >> 3;

    // Fill mapping: thread = (cbl = tid&3, cm = tid>>2), 16 t-values.
    // t-quad slot XOR'd by (cm&3) (matched by compute reads).
    const int cbl = tid & 3, cm = tid >> 2;
    const int cmx = cm & 3;

    if (tile0 < ntiles) {
        const float* src = x + (tile0 * TILE_T) * 1024 + cm * 32 + 4 * s + cbl;
        unsigned dst = sbase + (cbl * BROWS + cm * 16) * 4;
        #pragma unroll
        for (int t = 0; t < 16; t++) {
            int tslot = (t & 3) | ((((t >> 2) ^ cmx) & 3) << 2);
            cp_async4(dst + tslot * 4, src + t * 1024);
        }
    }
    cp_commit();

    int cur = 0;
    for (int tile = tile0; tile < ntiles; tile += tstep) {
        cp_wait0();                      // buf[cur] fully landed
        __syncthreads();                 // ... and prev tile's reads all done

        // Issue next tile into buf[cur^1]; overlaps this tile's compute.
        int nxt = tile + tstep;
        if (nxt < ntiles) {
            const float* src = x + (nxt * TILE_T) * 1024 + cm * 32 + 4 * s + cbl;
            unsigned dst = sbase + ((cur ^ 1) * XS_FLOATS + cbl * BROWS + cm * 16) * 4;
            #pragma unroll
            for (int t = 0; t < 16; t++) {
                int tslot = (t & 3) | ((((t >> 2) ^ cmx) & 3) << 2);
                cp_async4(dst + tslot * 4, src + t * 1024);
            }
        }
        cp_commit();

        uint64_t accD[2][2], accS[2][2];
        #pragma unroll
        for (int p = 0; p < 2; p++)
            #pragma unroll
            for (int tp = 0; tp < 2; tp++) { accD[p][tp] = 0; accS[p][tp] = 0; }

        const float* xw = sm + cur * XS_FLOATS + warp * BROWS;
        #pragma unroll
        for (int m = 0; m < 32; m++) {
            ulonglong2 xv = *(const ulonglong2*)(xw + m * 16 + ((th ^ (m & 3)) << 2));
            mma_core(Wp, m, xv, accD, accS);
        }

        // Un-diagonalize and store rows (STG.128, fully coalesced per instr).
        float* gp = g_h2 + tile * 16384 + b * 512 + 4 * th;
        #pragma unroll
        for (int p = 0; p < 2; p++) {
            float2 D0 = bc2(accD[p][0]), S0 = bc2(accS[p][0]);
            float2 D1 = bc2(accD[p][1]), S1 = bc2(accS[p][1]);
            float4 rA = make_float4(D0.x, S0.x, D1.x, S1.x);  // row 2p
            float4 rB = make_float4(S0.y, D0.y, S1.y, D1.y);  // row 2p+1
            *(float4*)(gp + (nh + 8 * (2 * p)) * 16)     = rA;
            *(float4*)(gp + (nh + 8 * (2 * p + 1)) * 16) = rB;
        }

        cur ^= 1;   // next iter's sync fences these reads before refill
    }
}

__global__ __launch_bounds__(128, 3)
void monarch_stage2(const float* __restrict__ R, float* __restrict__ out,
                    int ntiles) {
    extern __shared__ float sm[];        // buf0|buf1 : hs[jl][m][tq] ; then os
    float* os = sm + 2 * XS_FLOATS;      // os[t][i][jl] : t*132 + i*4 + jl
    const int tid  = threadIdx.x;
    const int warp = tid >> 5;           // jl in [0,4)
    const int lane = tid & 31;
    const int ih = lane & 7, th = lane >> 3;
    const int s  = blockIdx.x & 7;       // eighth: j in [4s, 4s+4)
    const int j  = 4 * s + warp;

    uint64_t Wp[2][32];
    load_wpacked(R + j * 1024, ih, Wp);

    const unsigned sbase = smem_addr(sm);
    const int tstep = gridDim.x >> 3;
    const int tile0 = blockIdx.x >> 3;

    // Fill: hs[jl][m][tq-slot] = g_h2[tile][m][4s+jl][tq], slot = tq ^ jl.
    // e = tid + k*128: tq = e&3, jl = (e>>2)&3, m = e>>4.
    const int ctq = tid & 3, cjl = (tid >> 2) & 3, cmv = tid >> 4;

    if (tile0 < ntiles) {
        #pragma unroll
        for (int k = 0; k < 4; k++) {
            int m = cmv + k * 8;
            const float* src = g_h2 + tile0 * 16384 + m * 512 + (4 * s + cjl) * 16 + ctq * 4;
            unsigned dst = sbase + (cjl * BROWS + m * 16 + ((ctq ^ cjl) << 2)) * 4;
            cp_async16(dst, src);
        }
    }
    cp_commit();

    int cur = 0;
    for (int tile = tile0; tile < ntiles; tile += tstep) {
        cp_wait0();
        __syncthreads();                 // hs[cur] ready; prev flush reads done

        int nxt = tile + tstep;
        if (nxt < ntiles) {
            #pragma unroll
            for (int k = 0; k < 4; k++) {
                int m = cmv + k * 8;
                const float* src = g_h2 + nxt * 16384 + m * 512 + (4 * s + cjl) * 16 + ctq * 4;
                unsigned dst = sbase + ((cur ^ 1) * XS_FLOATS
                               + cjl * BROWS + m * 16 + ((ctq ^ cjl) << 2)) * 4;
                cp_async16(dst, src);
            }
        }
        cp_commit();

        uint64_t accD[2][2], accS[2][2];
        #pragma unroll
        for (int p = 0; p < 2; p++)
            #pragma unroll
            for (int tp = 0; tp < 2; tp++) { accD[p][tp] = 0; accS[p][tp] = 0; }

        const float* hw = sm + cur * XS_FLOATS + warp * BROWS;
        #pragma unroll
        for (int m = 0; m < 32; m++) {
            ulonglong2 hv = *(const ulonglong2*)(hw + m * 16 + ((th ^ warp) << 2));
            mma_core(Wp, m, hv, accD, accS);
        }

        // Stage rows to os (scalar STS, ~2-way).
        #pragma unroll
        for (int p = 0; p < 2; p++) {
            float2 D0 = bc2(accD[p][0]), S0 = bc2(accS[p][0]);
            float2 D1 = bc2(accD[p][1]), S1 = bc2(accS[p][1]);
            float rA[4] = {D0.x, S0.x, D1.x, S1.x};   // i = ih + 8*(2p)
            float rB[4] = {S0.y, D0.y, S1.y, D1.y};   // i = ih + 8*(2p+1)
            float* oA = os + (ih + 8 * (2 * p)) * 4 + warp;
            float* oB = os + (ih + 8 * (2 * p + 1)) * 4 + warp;
            #pragma unroll
            for (int dt = 0; dt < 4; dt++) {
                oA[(4 * th + dt) * 132] = rA[dt];
                oB[(4 * th + dt) * 132] = rB[dt];
            }
        }
        __syncthreads();                 // os staged (also fences hs[cur] reads)

        // Flush: LDS.128 + STG.128, out[t][i*32 + 4s + jl].
        const int t0 = tile * TILE_T;
        #pragma unroll
        for (int k = 0; k < 4; k++) {
            int e = tid + k * 128;       // e in [0,512): i = e&31, t = e>>5
            int i2 = e & 31, t = e >> 5;
            float4 v = *(const float4*)(os + t * 132 + i2 * 4);
            *(float4*)(out + (t0 + t) * 1024 + i2 * 32 + 4 * s) = v;
        }
        // os reuse next tile fenced by loop-top __syncthreads.
        cur ^= 1;
    }
}

extern "C" void kernel_launch(void* const* d_in, const int* in_sizes, int n_in,
                              void* d_out, int out_size) {
    const float* x = (const float*)d_in[0];
    const float* L = (const float*)d_in[1];
    const float* R = (const float*)d_in[2];
    float* out = (float*)d_out;

    const int ntok   = in_sizes[0] / 1024;   // 32768
    const int ntiles = ntok / TILE_T;        // 2048

    cudaFuncSetAttribute(monarch_stage1,
                         cudaFuncAttributeMaxDynamicSharedMemorySize, SMEM1_BYTES);
    cudaFuncSetAttribute(monarch_stage2,
                         cudaFuncAttributeMaxDynamicSharedMemorySize, SMEM2_BYTES);

    int sms = 148;
    cudaDeviceGetAttribute(&sms, cudaDevAttrMultiProcessorCount, 0);
    int grid = 8 * ((3 * sms) / 8);          // 8 eighths, 3 CTAs/SM

    monarch_stage1<<<grid, 128, SMEM1_BYTES>>>(x, L, ntiles);
    monarch_stage2<<<grid, 128, SMEM2_BYTES>>>(R, out, ntiles);
}

// round 12
// speedup vs baseline: 1.0728x; 1.0728x over previous
#include <cuda_runtime.h>
#include <cstdint>

// MonarchOutProjection:
//   h2[t][b][n]    = sum_m L[b][n][m] * x[t][m*32+b]
//   out[t][i*32+j] = sum_m R[j][i][m] * h2[t][m][j]
//
// R11 = R9 compute (R=2 rows/thread, 64 weight regs, FFMA2) with finer CTAs:
// 128 threads, 4 CTAs/SM (same 16 warps/SM), CTA owns an eighth (4 blocks).
// Narrower barriers + 4 independent CTA pipelines per SM attack the measured
// ~2x latency gap (issue 27.6%, no pipe saturated).

#define TILE_T 16
#define BROW 516                        // per-block smem row: 32m*16t + 4
#define XS_FLOATS (4 * BROW)            // 2064 per buffer (4 blocks / eighth)
#define OS_FLOATS (16 * 132)            // 2112: os[t][i][jl] = t*132 + i*4 + jl
#define SMEM1_BYTES (2 * XS_FLOATS * 4)                 // 16512
#define SMEM2_BYTES ((2 * XS_FLOATS + OS_FLOATS) * 4)   // 24960

// g_h2[tile][b][n][t] : idx = tile*16384 + b*512 + n*16 + t
__device__ float g_h2[33554432];

__device__ __forceinline__ unsigned smem_addr(const void* p) {
    return (unsigned)__cvta_generic_to_shared(p);
}
__device__ __forceinline__ void cp_async4(unsigned dst, const float* src) {
    asm volatile("cp.async.ca.shared.global [%0], [%1], 4;" :: "r"(dst), "l"(src));
}
__device__ __forceinline__ void cp_async16(unsigned dst, const float* src) {
    asm volatile("cp.async.cg.shared.global [%0], [%1], 16;" :: "r"(dst), "l"(src));
}
__device__ __forceinline__ void cp_commit() {
    asm volatile("cp.async.commit_group;");
}
__device__ __forceinline__ void cp_wait1() {
    asm volatile("cp.async.wait_group 1;");
}
__device__ __forceinline__ void ffma2(uint64_t& acc, uint64_t a, uint64_t b) {
    asm("fma.rn.f32x2 %0, %1, %2, %0;" : "+l"(acc) : "l"(a), "l"(b));
}
__device__ __forceinline__ uint64_t splat2(float w) {
    uint64_t r;
    asm("mov.b64 %0, {%1, %1};" : "=l"(r) : "f"(w));
    return r;
}

__global__ __launch_bounds__(128, 4)
void monarch_stage1(const float* __restrict__ x, const float* __restrict__ L,
                    int ntiles) {
    extern __shared__ float sm[];        // buf0|buf1 : xs[bl][m][t-slot]
    const int tid  = threadIdx.x;
    const int warp = tid >> 5;           // bl in [0,4)
    const int lane = tid & 31;
    const int nh = lane & 15, th = lane >> 4;
    const int s  = blockIdx.x & 7;       // eighth: blocks [4s, 4s+4)
    const int b  = 4 * s + warp;

    // Weights (once): Lr[r][m] = L[b][nh + 16r][m]  (64 regs)
    float Lr[2][32];
    #pragma unroll
    for (int r = 0; r < 2; r++) {
        const float4* Lp = (const float4*)(L + b * 1024 + (nh + 16 * r) * 32);
        #pragma unroll
        for (int g = 0; g < 8; g++) {
            float4 v = Lp[g];
            Lr[r][4*g+0] = v.x; Lr[r][4*g+1] = v.y;
            Lr[r][4*g+2] = v.z; Lr[r][4*g+3] = v.w;
        }
    }

    const unsigned sbase = smem_addr(sm);
    const int tstep = gridDim.x >> 3;
    const int tile0 = blockIdx.x >> 3;

    // Fill mapping: thread = (cbl = tid&3, cm = tid>>2), 16 t-values, 4B each.
    // t-quad slot XOR'd by (cm&3) -> STS stays 2-way; compute reads match.
    const int cbl = tid & 3, cm = tid >> 2;
    const int cmx = cm & 3;

    if (tile0 < ntiles) {
        const float* src = x + (tile0 * TILE_T) * 1024 + cm * 32 + 4 * s + cbl;
        unsigned dst = sbase + (cbl * BROW + cm * 16) * 4;
        #pragma unroll
        for (int t = 0; t < 16; t++) {
            int tslot = (t & 3) | ((((t >> 2) ^ cmx) & 3) << 2);
            cp_async4(dst + tslot * 4, src + t * 1024);
        }
    }
    cp_commit();

    int cur = 0;
    for (int tile = tile0; tile < ntiles; tile += tstep) {
        int nxt = tile + tstep;
        if (nxt < ntiles) {
            const float* src = x + (nxt * TILE_T) * 1024 + cm * 32 + 4 * s + cbl;
            unsigned dst = sbase + ((cur ^ 1) * XS_FLOATS + cbl * BROW + cm * 16) * 4;
            #pragma unroll
            for (int t = 0; t < 16; t++) {
                int tslot = (t & 3) | ((((t >> 2) ^ cmx) & 3) << 2);
                cp_async4(dst + tslot * 4, src + t * 1024);
            }
        }
        cp_commit();
        cp_wait1();                      // buf[cur] landed
        __syncthreads();

        // acc[r][p] covers n = nh+16r, t = 8*th + 2p, 2p+1
        uint64_t acc[2][4];
        #pragma unroll
        for (int r = 0; r < 2; r++)
            #pragma unroll
            for (int p = 0; p < 4; p++) acc[r][p] = 0ull;

        const float* xw = sm + cur * XS_FLOATS + warp * BROW;
        #pragma unroll
        for (int m = 0; m < 32; m++) {
            const ulonglong2* xq = (const ulonglong2*)(xw + m * 16);
            ulonglong2 xv0 = xq[(2 * th)     ^ (m & 3)];   // t-quad 2th
            ulonglong2 xv1 = xq[(2 * th + 1) ^ (m & 3)];   // t-quad 2th+1
            uint64_t w0 = splat2(Lr[0][m]);
            uint64_t w1 = splat2(Lr[1][m]);
            ffma2(acc[0][0], w0, xv0.x); ffma2(acc[0][1], w0, xv0.y);
            ffma2(acc[0][2], w0, xv1.x); ffma2(acc[0][3], w0, xv1.y);
            ffma2(acc[1][0], w1, xv0.x); ffma2(acc[1][1], w1, xv0.y);
            ffma2(acc[1][2], w1, xv1.x); ffma2(acc[1][3], w1, xv1.y);
        }

        // Store: g_h2[tile][b][n][t]; warp covers 1KB contiguous per (r, STG).
        float* gp = g_h2 + tile * 16384 + b * 512 + th * 8;
        #pragma unroll
        for (int r = 0; r < 2; r++) {
            float* rp = gp + (nh + 16 * r) * 16;
            ulonglong2 v0; v0.x = acc[r][0]; v0.y = acc[r][1];
            ulonglong2 v1; v1.x = acc[r][2]; v1.y = acc[r][3];
            *(ulonglong2*)(rp)     = v0;     // t = 8th+0..3
            *(ulonglong2*)(rp + 4) = v1;     // t = 8th+4..7
        }

        // Fence buf[cur] reads before the next iteration's cp.async refill.
        __syncthreads();

        cur ^= 1;
    }
}

__global__ __launch_bounds__(128, 4)
void monarch_stage2(const float* __restrict__ R, float* __restrict__ out,
                    int ntiles) {
    extern __shared__ float sm[];        // buf0|buf1 : hs[jl][m][t-slot] ; then os
    float* os = sm + 2 * XS_FLOATS;      // os[t][i][jl] : t*132 + i*4 + jl
    const int tid  = threadIdx.x;
    const int warp = tid >> 5;           // jl in [0,4)
    const int lane = tid & 31;
    const int nh = lane & 15, th = lane >> 4;
    const int s  = blockIdx.x & 7;       // eighth: j in [4s, 4s+4)
    const int j  = 4 * s + warp;

    // Weights (once): Rr[r][m] = R[j][nh + 16r][m]
    float Rr[2][32];
    #pragma unroll
    for (int r = 0; r < 2; r++) {
        const float4* Rp = (const float4*)(R + j * 1024 + (nh + 16 * r) * 32);
        #pragma unroll
        for (int g = 0; g < 8; g++) {
            float4 v = Rp[g];
            Rr[r][4*g+0] = v.x; Rr[r][4*g+1] = v.y;
            Rr[r][4*g+2] = v.z; Rr[r][4*g+3] = v.w;
        }
    }

    const unsigned sbase = smem_addr(sm);
    const int tstep = gridDim.x >> 3;
    const int tile0 = blockIdx.x >> 3;

    // Fill: e = tid + 128k (k<4): ctq = e&3, cjl = (e>>2)&3, m = e>>4.
    // hs[cjl][m][tq-slot] = g_h2[tile][m][4s+cjl][4ctq..4ctq+4], slot = ctq^cjl.
    const int ctq = tid & 3, cjl = (tid >> 2) & 3, cmb = tid >> 4;

    if (tile0 < ntiles) {
        #pragma unroll
        for (int k = 0; k < 4; k++) {
            int m = cmb + k * 8;
            const float* src = g_h2 + tile0 * 16384 + m * 512 + (4 * s + cjl) * 16 + ctq * 4;
            unsigned dst = sbase + (cjl * BROW + m * 16 + ((ctq ^ cjl) << 2)) * 4;
            cp_async16(dst, src);
        }
    }
    cp_commit();

    int cur = 0;
    for (int tile = tile0; tile < ntiles; tile += tstep) {
        int nxt = tile + tstep;
        if (nxt < ntiles) {
            #pragma unroll
            for (int k = 0; k < 4; k++) {
                int m = cmb + k * 8;
                const float* src = g_h2 + nxt * 16384 + m * 512 + (4 * s + cjl) * 16 + ctq * 4;
                unsigned dst = sbase + ((cur ^ 1) * XS_FLOATS
                               + cjl * BROW + m * 16 + ((ctq ^ cjl) << 2)) * 4;
                cp_async16(dst, src);
            }
        }
        cp_commit();
        cp_wait1();
        __syncthreads();                 // hs[cur] ready; prev flush reads done

        uint64_t acc[2][4];
        #pragma unroll
        for (int r = 0; r < 2; r++)
            #pragma unroll
            for (int p = 0; p < 4; p++) acc[r][p] = 0ull;

        const float* hw = sm + cur * XS_FLOATS + warp * BROW;
        #pragma unroll
        for (int m = 0; m < 32; m++) {
            const ulonglong2* hq = (const ulonglong2*)(hw + m * 16);
            ulonglong2 hv0 = hq[(2 * th)     ^ warp];      // slot = tq ^ jl
            ulonglong2 hv1 = hq[(2 * th + 1) ^ warp];
            uint64_t w0 = splat2(Rr[0][m]);
            uint64_t w1 = splat2(Rr[1][m]);
            ffma2(acc[0][0], w0, hv0.x); ffma2(acc[0][1], w0, hv0.y);
            ffma2(acc[0][2], w0, hv1.x); ffma2(acc[0][3], w0, hv1.y);
            ffma2(acc[1][0], w1, hv0.x); ffma2(acc[1][1], w1, hv0.y);
            ffma2(acc[1][2], w1, hv1.x); ffma2(acc[1][3], w1, hv1.y);
        }

        // Stage to os[t][i][jl] (2-way STS); barrier also fences hs[cur] reads
        // against next iteration's refill.
        #pragma unroll
        for (int r = 0; r < 2; r++) {
            float* op = os + (nh + 16 * r) * 4 + warp;
            #pragma unroll
            for (int p = 0; p < 4; p++) {
                float2 pr; *(uint64_t*)&pr = acc[r][p];
                op[(8 * th + 2 * p + 0) * 132] = pr.x;
                op[(8 * th + 2 * p + 1) * 132] = pr.y;
            }
        }
        __syncthreads();

        // Flush: out[t][i*32 + 4s + jl]. Per k: all 128 threads cover one t
        // (i = tid>>2, jl = tid&3); os reads sequential (conflict-free),
        // STG warp footprint = 8 x 16B chunks.
        const int t0 = tile * TILE_T;
        const int fjl = tid & 3, fi = tid >> 2;
        #pragma unroll
        for (int k = 0; k < 16; k++) {
            out[(t0 + k) * 1024 + fi * 32 + 4 * s + fjl] = os[k * 132 + fi * 4 + fjl];
        }
        // os reuse next tile fenced by loop-top __syncthreads.
        cur ^= 1;
    }
}

extern "C" void kernel_launch(void* const* d_in, const int* in_sizes, int n_in,
                              void* d_out, int out_size) {
    const float* x = (const float*)d_in[0];
    const float* L = (const float*)d_in[1];
    const float* R = (const float*)d_in[2];
    float* out = (float*)d_out;

    const int ntok   = in_sizes[0] / 1024;   // 32768
    const int ntiles = ntok / TILE_T;        // 2048

    cudaFuncSetAttribute(monarch_stage1,
                         cudaFuncAttributeMaxDynamicSharedMemorySize, SMEM1_BYTES);
    cudaFuncSetAttribute(monarch_stage2,
                         cudaFuncAttributeMaxDynamicSharedMemorySize, SMEM2_BYTES);

    int sms = 148;
    cudaDeviceGetAttribute(&sms, cudaDevAttrMultiProcessorCount, 0);
    int grid = 8 * ((4 * sms) / 8);          // 8 eighths, 4 CTAs/SM

    monarch_stage1<<<grid, 128, SMEM1_BYTES>>>(x, L, ntiles);
    monarch_stage2<<<grid, 128, SMEM2_BYTES>>>(R, out, ntiles);
}